// round 16
// baseline (speedup 1.0000x reference)
#include <cuda_runtime.h>
#include <cuda_fp16.h>
#include <math.h>
#include <stdint.h>

#define BATCH 4
#define CH    256
#define FH    100
#define FW    152
#define HW    (FH*FW)          // 15200
#define NROIS 512
#define OH    7
#define OW    7
#define NBIN  49
#define FDIM  (CH*NBIN)        // 12544
#define DFC   1024
#define NOFF  98               // 2*49
#define NOFFP 128              // padded for GEMM3
#define SCALE 0.0625f
#define GAMMA 0.1f
#define SKMAX 8

// ---------------- scratch (device globals; no allocation allowed) -----------
__device__ __half g_feath[(size_t)BATCH*HW*CH];  // NHWC fp16 features, 31 MB
__device__ __half g_a1h[(size_t)NROIS*FDIM];     // half(xcls) 12.8 MB
__device__ __half g_w1h[(size_t)DFC*FDIM];       // half(w1) 25.7 MB
__device__ __half g_w2h[(size_t)DFC*DFC];        // half(w2) 2 MB
__device__ __half g_w3h[(size_t)NOFFP*DFC];      // half(w3), zero-padded rows
__device__ __half g_h1h[NROIS*DFC];
__device__ __half g_h2h[NROIS*DFC];
__device__ float  g_off[NROIS*NOFF];
__device__ float  g_nrois[NROIS*5];
__device__ float  g_dots[NROIS*8];               // rescale partial dots [roi][cb][4]
__device__ float  g_part[(size_t)SKMAX*NROIS*DFC]; // split-K partials (16 MB)
__device__ int    g_cnt[64];                     // per-tile split-K counters (zero-init)

// ---------------- NCHW -> NHWC fp16 transpose -------------------------------
__global__ void nchw2nhwc_h(const float* __restrict__ in) {
    __shared__ float tile[64][33];
    int b   = blockIdx.z;
    int hw0 = blockIdx.x * 32;
    int c0  = blockIdx.y * 64;
    #pragma unroll
    for (int r = 0; r < 8; r++) {
        int c  = c0 + threadIdx.y + r*8;
        int hw = hw0 + threadIdx.x;
        tile[threadIdx.y + r*8][threadIdx.x] = in[((size_t)b*CH + c)*HW + hw];
    }
    __syncthreads();
    __half2* out2 = (__half2*)g_feath;
    #pragma unroll
    for (int r = 0; r < 4; r++) {
        int hwl = threadIdx.y + r*8;
        int hw  = hw0 + hwl;
        int c2  = threadIdx.x;
        float lo = tile[2*c2][hwl];
        float hi = tile[2*c2+1][hwl];
        out2[((size_t)b*HW + hw)*(CH/2) + c0/2 + c2] = __floats2half2_rn(lo, hi);
    }
}

// ---------------- fp32 -> fp16 weight conversion helpers --------------------
__device__ __forceinline__ uint32_t h2u(__half2 h) { return *reinterpret_cast<uint32_t*>(&h); }
__device__ __forceinline__ uint4 f8toh8(const float4* s) {
    float4 a = s[0], b = s[1];
    uint4 o;
    o.x = h2u(__floats2half2_rn(a.x, a.y));
    o.y = h2u(__floats2half2_rn(a.z, a.w));
    o.z = h2u(__floats2half2_rn(b.x, b.y));
    o.w = h2u(__floats2half2_rn(b.z, b.w));
    return o;
}

#define W1_8 (DFC*FDIM/8)
#define W2_8 (DFC*DFC/8)
#define W3_8 (NOFFP*DFC/8)
#define WTOT8 (W1_8 + W2_8 + W3_8)

__device__ __forceinline__ void cvt_one(int i, const float* w1, const float* w2,
                                        const float* w3) {
    if (i < W1_8) {
        ((uint4*)g_w1h)[i] = f8toh8((const float4*)(w1 + (size_t)i*8));
    } else if (i < W1_8 + W2_8) {
        int j = i - W1_8;
        ((uint4*)g_w2h)[j] = f8toh8((const float4*)(w2 + (size_t)j*8));
    } else {
        int j = i - W1_8 - W2_8;
        int r = (j*8) >> 10;
        uint4 o;
        if (r < NOFF) o = f8toh8((const float4*)(w3 + (size_t)j*8));
        else          o.x = o.y = o.z = o.w = 0u;
        ((uint4*)g_w3h)[j] = o;
    }
}

// ------- deformable RoI pool: 2 CTAs per ROI (128 channels each) ------------
#define POOL_CH   128
#define POOL_HALF (POOL_CH*NBIN)     // 6272 floats per half
#define PH4       (POOL_HALF/4)      // 1568
template<bool HAS_OFF, bool EMIT_HALF, bool RESCALE, bool DO_CVT>
__global__ void roi_pool(const float* __restrict__ rois,
                         const float* __restrict__ off,
                         float* __restrict__ out,
                         __half* __restrict__ out_h,
                         const float4* __restrict__ rw4,
                         const float* __restrict__ w1,
                         const float* __restrict__ w2,
                         const float* __restrict__ w3) {
    __shared__ float sout[POOL_HALF];         // 25 KB
    int tid = threadIdx.x;
    if (DO_CVT && blockIdx.y == 2) {
        const int stride = NROIS * 256;
        for (int i = blockIdx.x*256 + tid; i < WTOT8; i += stride)
            cvt_one(i, w1, w2, w3);
        return;
    }
    int roi = blockIdx.x;
    int cb  = blockIdx.y;                      // channel half: 0 or 1
    int bq = tid >> 4, cg = tid & 15;          // bin slot, 8-ch group (within half)
    const float* r = rois + roi*5;
    int   b  = (int)r[0];
    float x1 = r[1]*SCALE - 0.5f;
    float y1 = r[2]*SCALE - 0.5f;
    float x2 = r[3]*SCALE - 0.5f;
    float y2 = r[4]*SCALE - 0.5f;
    float rw = x2 - x1, rh = y2 - y1;
    float bw = rw * (1.0f/OW), bh = rh * (1.0f/OH);
    const uint4* fb = (const uint4*)(g_feath + (size_t)b*HW*CH);
    const int C8 = CH/8;                       // 32 uint4 per pixel
    int cgl = cb*16 + cg;                      // global 8-ch group index

    for (int b0 = 0; b0 < NBIN; b0 += 16) {
        int bin = b0 + bq;
        if (bin < NBIN) {
            int ph = bin / OW, pw = bin - ph*OW;
            float sw_ = x1, sh_ = y1;
            if (HAS_OFF) {
                sw_ += GAMMA * rw * off[roi*NOFF + bin];
                sh_ += GAMMA * rh * off[roi*NOFF + NBIN + bin];
            }
            float acc[8] = {};
            #pragma unroll
            for (int iy = 0; iy < 2; iy++) {
                float y = sh_ + ((float)ph + ((float)iy + 0.5f)*0.5f) * bh;
                #pragma unroll
                for (int ix = 0; ix < 2; ix++) {
                    float x = sw_ + ((float)pw + ((float)ix + 0.5f)*0.5f) * bw;
                    if (y > -1.0f && y < (float)FH && x > -1.0f && x < (float)FW) {
                        float yc = fminf(fmaxf(y, 0.0f), (float)(FH-1));
                        float xc = fminf(fmaxf(x, 0.0f), (float)(FW-1));
                        int y0 = min((int)floorf(yc), FH-2);
                        int x0 = min((int)floorf(xc), FW-2);
                        float ly = yc - (float)y0, lx = xc - (float)x0;
                        float hy = 1.0f - ly,     hx = 1.0f - lx;
                        float w00 = hy*hx, w01 = hy*lx, w10 = ly*hx, w11 = ly*lx;
                        const uint4* p = fb + ((size_t)y0*FW + x0)*C8 + cgl;
                        uint4 v00 = p[0];
                        uint4 v01 = p[C8];
                        uint4 v10 = p[FW*C8];
                        uint4 v11 = p[FW*C8 + C8];
                        const uint32_t* u00 = &v00.x;
                        const uint32_t* u01 = &v01.x;
                        const uint32_t* u10 = &v10.x;
                        const uint32_t* u11 = &v11.x;
                        #pragma unroll
                        for (int q = 0; q < 4; q++) {
                            float2 f00 = __half22float2(*(const __half2*)&u00[q]);
                            float2 f01 = __half22float2(*(const __half2*)&u01[q]);
                            float2 f10 = __half22float2(*(const __half2*)&u10[q]);
                            float2 f11 = __half22float2(*(const __half2*)&u11[q]);
                            acc[2*q]   += w00*f00.x + w01*f01.x + w10*f10.x + w11*f11.x;
                            acc[2*q+1] += w00*f00.y + w01*f01.y + w10*f10.y + w11*f11.y;
                        }
                    }
                }
            }
            int c = cg*8;                      // local channel within this half
            #pragma unroll
            for (int j = 0; j < 8; j++)
                sout[(c+j)*NBIN + bin] = acc[j] * 0.25f;
        }
    }
    __syncthreads();
    size_t base = (size_t)roi * FDIM + (size_t)cb * POOL_HALF;
    float* o = out + base;
    if (EMIT_HALF) {
        __half* oh = out_h + base;
        for (int i = tid; i < POOL_HALF; i += 256) {
            float v = sout[i];
            o[i] = v;
            oh[i] = __float2half_rn(v);
        }
    } else {
        for (int i = tid; i < POOL_HALF; i += 256) o[i] = sout[i];
    }

    if (RESCALE) {
        const float4* s4 = (const float4*)sout;
        int wo = cb * PH4;
        float s[4] = {0.f, 0.f, 0.f, 0.f};
        for (int k = tid; k < PH4; k += 256) {
            float4 v = s4[k];
            #pragma unroll
            for (int j = 0; j < 4; j++) {
                float4 a = rw4[(size_t)j*(FDIM/4) + wo + k];
                s[j] += v.x*a.x + v.y*a.y + v.z*a.z + v.w*a.w;
            }
        }
        #pragma unroll
        for (int o2 = 16; o2 > 0; o2 >>= 1)
            #pragma unroll
            for (int j = 0; j < 4; j++)
                s[j] += __shfl_down_sync(0xffffffffu, s[j], o2);
        __shared__ float red[4][8];
        int lane = tid & 31, warp = tid >> 5;
        if (lane == 0) { red[0][warp]=s[0]; red[1][warp]=s[1]; red[2][warp]=s[2]; red[3][warp]=s[3]; }
        __syncthreads();
        if (tid < 4) {
            float t = 0.f;
            #pragma unroll
            for (int ww = 0; ww < 8; ww++) t += red[tid][ww];
            g_dots[roi*8 + cb*4 + tid] = t;
        }
    }
}

// ------------ fp16 tensor-core NT GEMM, 128x128x32, 3-stage cp.async --------
// RED: fused deterministic split-K reduction — last CTA per tile sums the S
// fp32 partials (fixed order), adds bias, relu, writes fp16 h, resets counter.
__device__ __forceinline__ void mma_f16(float* c, uint32_t a0, uint32_t a1,
                                        uint32_t a2, uint32_t a3,
                                        uint32_t b0, uint32_t b1) {
    asm volatile(
        "mma.sync.aligned.m16n8k16.row.col.f32.f16.f16.f32 "
        "{%0,%1,%2,%3}, {%4,%5,%6,%7}, {%8,%9}, {%0,%1,%2,%3};"
        : "+f"(c[0]), "+f"(c[1]), "+f"(c[2]), "+f"(c[3])
        : "r"(a0), "r"(a1), "r"(a2), "r"(a3), "r"(b0), "r"(b1));
}
__device__ __forceinline__ uint32_t s2u(const void* p) {
    return (uint32_t)__cvta_generic_to_shared(p);
}
__device__ __forceinline__ void cp16(uint32_t dst, const void* src) {
    asm volatile("cp.async.cg.shared.global [%0], [%1], 16;" :: "r"(dst), "l"(src));
}

template<bool RED>
__global__ void __launch_bounds__(256, 2)
gemm_h(const __half* __restrict__ A, const __half* __restrict__ B,
       float* __restrict__ P, int N, int K,
       __half* __restrict__ outh, const float* __restrict__ bias) {
    const int BM = 128, BN = 128;
    __shared__ __align__(16) uint32_t As[3][BM*16];
    __shared__ __align__(16) uint32_t Bs[3][BN*16];

    int tid  = threadIdx.x;
    int lane = tid & 31, w = tid >> 5;
    int g = lane >> 2, tig = lane & 3;
    int wm = w >> 2, wn = w & 3;               // 2 x 4 warp grid
    int bm = blockIdx.y * BM, bn = blockIdx.x * BN;
    int S  = gridDim.z, kz = blockIdx.z;
    int Ks = K / S;
    int M  = gridDim.y * BM;
    int nst = Ks >> 5;

    int lm = tid >> 2, lq = tid & 3;
    const __half* Ap0 = A + (size_t)(bm + lm)*K + (size_t)kz*Ks + lq*8;
    const __half* Ap1 = Ap0 + (size_t)64*K;
    const __half* Bp0 = B + (size_t)(bn + lm)*K + (size_t)kz*Ks + lq*8;
    const __half* Bp1 = Bp0 + (size_t)64*K;
    int sc = lq ^ ((lm >> 1) & 3);
    int sw0 = lm*16 + sc*4;
    int sw1 = (lm + 64)*16 + sc*4;
    uint32_t sa0[3], sa1[3], sb0[3], sb1[3];
    #pragma unroll
    for (int b3 = 0; b3 < 3; b3++) {
        sa0[b3] = s2u(&As[b3][sw0]);  sa1[b3] = s2u(&As[b3][sw1]);
        sb0[b3] = s2u(&Bs[b3][sw0]);  sb1[b3] = s2u(&Bs[b3][sw1]);
    }

    float acc[4][4][4];
    #pragma unroll
    for (int i = 0; i < 4; i++)
        #pragma unroll
        for (int j = 0; j < 4; j++)
            #pragma unroll
            for (int q = 0; q < 4; q++) acc[i][j][q] = 0.0f;

    int mrow[4], mj[4];
    #pragma unroll
    for (int ii = 0; ii < 4; ii++) {
        mrow[ii] = wm*64 + ii*16 + g;
        mj[ii] = ((mrow[ii] >> 1) & 3) << 2;
    }
    int nrow[4], nj[4];
    #pragma unroll
    for (int jj = 0; jj < 4; jj++) {
        nrow[jj] = wn*32 + jj*8 + g;
        nj[jj] = ((nrow[jj] >> 1) & 3) << 2;
    }

    cp16(sa0[0], Ap0);  cp16(sa1[0], Ap1);
    cp16(sb0[0], Bp0);  cp16(sb1[0], Bp1);
    asm volatile("cp.async.commit_group;");
    if (nst > 1) {
        cp16(sa0[1], Ap0 + 32);  cp16(sa1[1], Ap1 + 32);
        cp16(sb0[1], Bp0 + 32);  cp16(sb1[1], Bp1 + 32);
        asm volatile("cp.async.commit_group;");
    }

    int buf = 0;
    for (int s = 0; s < nst; s++) {
        if (s < nst - 1) asm volatile("cp.async.wait_group 1;");
        else             asm volatile("cp.async.wait_group 0;");
        __syncthreads();

        const uint32_t* as = As[buf];
        const uint32_t* bs = Bs[buf];
        #pragma unroll
        for (int kb = 0; kb < 2; kb++) {
            int kw0 = kb*8 + tig, kw1 = kw0 + 4;
            uint32_t af[4][4], bf[4][2];
            #pragma unroll
            for (int jj = 0; jj < 4; jj++) {
                int rn = nrow[jj]*16, x = nj[jj];
                bf[jj][0] = bs[rn + (kw0 ^ x)];
                bf[jj][1] = bs[rn + (kw1 ^ x)];
            }
            #pragma unroll
            for (int ii = 0; ii < 4; ii++) {
                int r0 = mrow[ii]*16, r1 = (mrow[ii]+8)*16, x = mj[ii];
                af[ii][0] = as[r0 + (kw0 ^ x)];
                af[ii][1] = as[r1 + (kw0 ^ x)];
                af[ii][2] = as[r0 + (kw1 ^ x)];
                af[ii][3] = as[r1 + (kw1 ^ x)];
            }
            #pragma unroll
            for (int ii = 0; ii < 4; ii++)
                #pragma unroll
                for (int jj = 0; jj < 4; jj++)
                    mma_f16(acc[ii][jj], af[ii][0], af[ii][1], af[ii][2], af[ii][3],
                            bf[jj][0], bf[jj][1]);
        }

        if (s + 2 < nst) {
            int nb = (buf + 2) % 3;
            size_t o = (size_t)(s+2)*32;
            cp16(sa0[nb], Ap0 + o);  cp16(sa1[nb], Ap1 + o);
            cp16(sb0[nb], Bp0 + o);  cp16(sb1[nb], Bp1 + o);
            asm volatile("cp.async.commit_group;");
        }
        buf = (buf + 1) % 3;
    }

    float* Pp = P + (size_t)kz * M * N;
    #pragma unroll
    for (int ii = 0; ii < 4; ii++) {
        #pragma unroll
        for (int jj = 0; jj < 4; jj++) {
            int r0 = bm + wm*64 + ii*16 + g;
            int c0 = bn + wn*32 + jj*8 + tig*2;
            Pp[(size_t)r0*N + c0]       = acc[ii][jj][0];
            Pp[(size_t)r0*N + c0 + 1]   = acc[ii][jj][1];
            Pp[(size_t)(r0+8)*N + c0]   = acc[ii][jj][2];
            Pp[(size_t)(r0+8)*N + c0+1] = acc[ii][jj][3];
        }
    }

    if (RED) {
        __threadfence();                       // release partial stores
        __syncthreads();
        __shared__ int sOld;
        int tileid = blockIdx.y * gridDim.x + blockIdx.x;
        if (tid == 0) sOld = atomicAdd(&g_cnt[tileid], 1);
        __syncthreads();
        if (sOld == S - 1) {
            __threadfence();                   // acquire other CTAs' partials
            const int NT4 = BM * BN / 4;       // 4096 float4 outputs
            for (int idx = tid; idx < NT4; idx += 256) {
                int row = idx >> 5;            // 32 float4 per row
                int c4  = (idx & 31) * 4;
                size_t o = (size_t)(bm + row) * N + bn + c4;
                float4 v = *(const float4*)(bias + bn + c4);
                for (int s2 = 0; s2 < S; s2++) {
                    float4 p = *(const float4*)(P + (size_t)s2*M*N + o);
                    v.x += p.x; v.y += p.y; v.z += p.z; v.w += p.w;
                }
                v.x = fmaxf(v.x, 0.f); v.y = fmaxf(v.y, 0.f);
                v.z = fmaxf(v.z, 0.f); v.w = fmaxf(v.w, 0.f);
                uint2 ov;
                ov.x = h2u(__floats2half2_rn(v.x, v.y));
                ov.y = h2u(__floats2half2_rn(v.z, v.w));
                *(uint2*)(outh + o) = ov;
            }
            if (tid == 0) g_cnt[tileid] = 0;   // replay-safe reset
        }
    }
}

// -------- final combine (float out, ragged N) + fused new-roi finalize ------
#define CF_BLOCKS ((NROIS*NOFF + 255)/256)    // 196
__global__ void combine_f_fin(const float* __restrict__ P, const float* __restrict__ bias,
                              float* __restrict__ outf, int M, int Ntot, int Nlog, int S,
                              const float* __restrict__ rois,
                              const float* __restrict__ rbias) {
    if (blockIdx.x >= CF_BLOCKS) {
        int roi = (blockIdx.x - CF_BLOCKS) * 256 + threadIdx.x;
        if (roi >= NROIS) return;
        float d[4];
        #pragma unroll
        for (int j = 0; j < 4; j++) {
            float t = g_dots[roi*8 + j] + g_dots[roi*8 + 4 + j] + rbias[j];
            d[j] = 1.0f + 0.5f / (1.0f + expf(-t));
        }
        const float* r = rois + roi*5;
        float cx = (r[1] + r[3]) * 0.5f + d[0];
        float cy = (r[2] + r[4]) * 0.5f + d[1];
        float nw = (r[3] - r[1]) * d[2];
        float nh = (r[4] - r[2]) * d[3];
        float* nr = g_nrois + roi*5;
        nr[0] = r[0];
        nr[1] = cx - 0.5f*nw;  nr[2] = cy - 0.5f*nh;
        nr[3] = cx + 0.5f*nw;  nr[4] = cy + 0.5f*nh;
        return;
    }
    int i = blockIdx.x * 256 + threadIdx.x;
    if (i >= M*Nlog) return;
    int m = i / Nlog, n = i - m*Nlog;
    float v = bias[n];
    for (int s = 0; s < S; s++)
        v += P[((size_t)s*M + m)*Ntot + n];
    outf[i] = v;
}

// ---------------- launch -----------------------------------------------------
extern "C" void kernel_launch(void* const* d_in, const int* in_sizes, int n_in,
                              void* d_out, int out_size) {
    const float* input     = (const float*)d_in[0];
    const float* rois      = (const float*)d_in[1];
    const float* rescale_w = (const float*)d_in[2];
    const float* rescale_b = (const float*)d_in[3];
    const float* off_w1    = (const float*)d_in[4];
    const float* off_b1    = (const float*)d_in[5];
    const float* off_w2    = (const float*)d_in[6];
    const float* off_b2    = (const float*)d_in[7];
    const float* off_w3    = (const float*)d_in[8];
    const float* off_b3    = (const float*)d_in[9];

    float* xcls = (float*)d_out;
    float* xreg = xcls + (size_t)NROIS * FDIM;

    __half *a1p, *w1p, *w2p, *w3p, *h1p, *h2p;
    float *offp, *nroisp, *partp;
    cudaGetSymbolAddress((void**)&a1p,    g_a1h);
    cudaGetSymbolAddress((void**)&w1p,    g_w1h);
    cudaGetSymbolAddress((void**)&w2p,    g_w2h);
    cudaGetSymbolAddress((void**)&w3p,    g_w3h);
    cudaGetSymbolAddress((void**)&h1p,    g_h1h);
    cudaGetSymbolAddress((void**)&h2p,    g_h2h);
    cudaGetSymbolAddress((void**)&offp,   g_off);
    cudaGetSymbolAddress((void**)&nroisp, g_nrois);
    cudaGetSymbolAddress((void**)&partp,  g_part);

    // 1) transpose to NHWC fp16
    nchw2nhwc_h<<<dim3(HW/32, CH/64, BATCH), dim3(32, 8)>>>(input);
    // 2) x_cls pool (2 CTAs/ROI) + rescale dots + fused weight conversion
    roi_pool<false,true,true,true><<<dim3(NROIS, 3), 256>>>(
        rois, nullptr, xcls, a1p, (const float4*)rescale_w,
        off_w1, off_w2, off_w3);
    // 3) offset MLP: fp16 tensor cores, fused split-K reduction in-epilogue
    gemm_h<true><<<dim3(DFC/128, NROIS/128, 8), 256>>>(
        a1p, w1p, partp, DFC, FDIM, h1p, off_b1);
    gemm_h<true><<<dim3(DFC/128, NROIS/128, 8), 256>>>(
        h1p, w2p, partp, DFC, DFC, h2p, off_b2);
    gemm_h<false><<<dim3(1, NROIS/128, 8), 256>>>(
        h2p, w3p, partp, NOFFP, DFC, nullptr, nullptr);
    // 4) final combine + fused new-roi finalize
    combine_f_fin<<<CF_BLOCKS + 2, 256>>>(partp, off_b3, offp, NROIS, NOFFP, NOFF, 8,
                                          rois, rescale_b);
    // 5) x_reg pool (2 CTAs/ROI) -> second half of d_out
    roi_pool<true,false,false,false><<<dim3(NROIS, 2), 256>>>(
        nroisp, offp, xreg, nullptr, nullptr, nullptr, nullptr, nullptr);
}

// round 17
// speedup vs baseline: 1.1349x; 1.1349x over previous
#include <cuda_runtime.h>
#include <cuda_fp16.h>
#include <math.h>
#include <stdint.h>

#define BATCH 4
#define CH    256
#define FH    100
#define FW    152
#define HW    (FH*FW)          // 15200
#define NROIS 512
#define OH    7
#define OW    7
#define NBIN  49
#define FDIM  (CH*NBIN)        // 12544
#define DFC   1024
#define NOFF  98               // 2*49
#define NOFFP 128              // padded for GEMM3
#define SCALE 0.0625f
#define GAMMA 0.1f
#define SKMAX 8

// ---------------- scratch (device globals; no allocation allowed) -----------
__device__ __half g_feath[(size_t)BATCH*HW*CH];  // NHWC fp16 features, 31 MB
__device__ __half g_a1h[(size_t)NROIS*FDIM];     // half(xcls) 12.8 MB
__device__ __half g_w1h[(size_t)DFC*FDIM];       // half(w1) 25.7 MB
__device__ __half g_w2h[(size_t)DFC*DFC];        // half(w2) 2 MB
__device__ __half g_w3h[(size_t)NOFFP*DFC];      // half(w3), zero-padded rows
__device__ __half g_h1h[NROIS*DFC];
__device__ __half g_h2h[NROIS*DFC];
__device__ float  g_off[NROIS*NOFF];
__device__ float  g_nrois[NROIS*5];
__device__ float  g_dots[NROIS*8];               // rescale partial dots [roi][cb][4]
__device__ __half g_parth[(size_t)SKMAX*NROIS*DFC]; // split-K partials, fp16 (8 MB)

// ---------------- NCHW -> NHWC fp16 transpose -------------------------------
__global__ void nchw2nhwc_h(const float* __restrict__ in) {
    __shared__ float tile[64][33];
    int b   = blockIdx.z;
    int hw0 = blockIdx.x * 32;
    int c0  = blockIdx.y * 64;
    #pragma unroll
    for (int r = 0; r < 8; r++) {
        int c  = c0 + threadIdx.y + r*8;
        int hw = hw0 + threadIdx.x;
        tile[threadIdx.y + r*8][threadIdx.x] = in[((size_t)b*CH + c)*HW + hw];
    }
    __syncthreads();
    __half2* out2 = (__half2*)g_feath;
    #pragma unroll
    for (int r = 0; r < 4; r++) {
        int hwl = threadIdx.y + r*8;
        int hw  = hw0 + hwl;
        int c2  = threadIdx.x;
        float lo = tile[2*c2][hwl];
        float hi = tile[2*c2+1][hwl];
        out2[((size_t)b*HW + hw)*(CH/2) + c0/2 + c2] = __floats2half2_rn(lo, hi);
    }
}

// ---------------- fp32 -> fp16 weight conversion helpers --------------------
__device__ __forceinline__ uint32_t h2u(__half2 h) { return *reinterpret_cast<uint32_t*>(&h); }
__device__ __forceinline__ uint4 f8toh8(const float4* s) {
    float4 a = s[0], b = s[1];
    uint4 o;
    o.x = h2u(__floats2half2_rn(a.x, a.y));
    o.y = h2u(__floats2half2_rn(a.z, a.w));
    o.z = h2u(__floats2half2_rn(b.x, b.y));
    o.w = h2u(__floats2half2_rn(b.z, b.w));
    return o;
}

#define W1_8 (DFC*FDIM/8)
#define W2_8 (DFC*DFC/8)
#define W3_8 (NOFFP*DFC/8)
#define WTOT8 (W1_8 + W2_8 + W3_8)

__device__ __forceinline__ void cvt_one(int i, const float* w1, const float* w2,
                                        const float* w3) {
    if (i < W1_8) {
        ((uint4*)g_w1h)[i] = f8toh8((const float4*)(w1 + (size_t)i*8));
    } else if (i < W1_8 + W2_8) {
        int j = i - W1_8;
        ((uint4*)g_w2h)[j] = f8toh8((const float4*)(w2 + (size_t)j*8));
    } else {
        int j = i - W1_8 - W2_8;
        int r = (j*8) >> 10;
        uint4 o;
        if (r < NOFF) o = f8toh8((const float4*)(w3 + (size_t)j*8));
        else          o.x = o.y = o.z = o.w = 0u;
        ((uint4*)g_w3h)[j] = o;
    }
}

// ------- deformable RoI pool: 2 CTAs per ROI (128 channels each) ------------
#define POOL_CH   128
#define POOL_HALF (POOL_CH*NBIN)     // 6272 floats per half
#define PH4       (POOL_HALF/4)      // 1568
template<bool HAS_OFF, bool EMIT_HALF, bool RESCALE, bool DO_CVT>
__global__ void roi_pool(const float* __restrict__ rois,
                         const float* __restrict__ off,
                         float* __restrict__ out,
                         __half* __restrict__ out_h,
                         const float4* __restrict__ rw4,
                         const float* __restrict__ w1,
                         const float* __restrict__ w2,
                         const float* __restrict__ w3) {
    __shared__ float sout[POOL_HALF];         // 25 KB
    int tid = threadIdx.x;
    if (DO_CVT && blockIdx.y == 2) {
        const int stride = NROIS * 256;
        for (int i = blockIdx.x*256 + tid; i < WTOT8; i += stride)
            cvt_one(i, w1, w2, w3);
        return;
    }
    int roi = blockIdx.x;
    int cb  = blockIdx.y;                      // channel half: 0 or 1
    int bq = tid >> 4, cg = tid & 15;          // bin slot, 8-ch group (within half)
    const float* r = rois + roi*5;
    int   b  = (int)r[0];
    float x1 = r[1]*SCALE - 0.5f;
    float y1 = r[2]*SCALE - 0.5f;
    float x2 = r[3]*SCALE - 0.5f;
    float y2 = r[4]*SCALE - 0.5f;
    float rw = x2 - x1, rh = y2 - y1;
    float bw = rw * (1.0f/OW), bh = rh * (1.0f/OH);
    const uint4* fb = (const uint4*)(g_feath + (size_t)b*HW*CH);
    const int C8 = CH/8;                       // 32 uint4 per pixel
    int cgl = cb*16 + cg;                      // global 8-ch group index

    for (int b0 = 0; b0 < NBIN; b0 += 16) {
        int bin = b0 + bq;
        if (bin < NBIN) {
            int ph = bin / OW, pw = bin - ph*OW;
            float sw_ = x1, sh_ = y1;
            if (HAS_OFF) {
                sw_ += GAMMA * rw * off[roi*NOFF + bin];
                sh_ += GAMMA * rh * off[roi*NOFF + NBIN + bin];
            }
            float acc[8] = {};
            #pragma unroll
            for (int iy = 0; iy < 2; iy++) {
                float y = sh_ + ((float)ph + ((float)iy + 0.5f)*0.5f) * bh;
                #pragma unroll
                for (int ix = 0; ix < 2; ix++) {
                    float x = sw_ + ((float)pw + ((float)ix + 0.5f)*0.5f) * bw;
                    if (y > -1.0f && y < (float)FH && x > -1.0f && x < (float)FW) {
                        float yc = fminf(fmaxf(y, 0.0f), (float)(FH-1));
                        float xc = fminf(fmaxf(x, 0.0f), (float)(FW-1));
                        int y0 = min((int)floorf(yc), FH-2);
                        int x0 = min((int)floorf(xc), FW-2);
                        float ly = yc - (float)y0, lx = xc - (float)x0;
                        float hy = 1.0f - ly,     hx = 1.0f - lx;
                        float w00 = hy*hx, w01 = hy*lx, w10 = ly*hx, w11 = ly*lx;
                        const uint4* p = fb + ((size_t)y0*FW + x0)*C8 + cgl;
                        uint4 v00 = p[0];
                        uint4 v01 = p[C8];
                        uint4 v10 = p[FW*C8];
                        uint4 v11 = p[FW*C8 + C8];
                        const uint32_t* u00 = &v00.x;
                        const uint32_t* u01 = &v01.x;
                        const uint32_t* u10 = &v10.x;
                        const uint32_t* u11 = &v11.x;
                        #pragma unroll
                        for (int q = 0; q < 4; q++) {
                            float2 f00 = __half22float2(*(const __half2*)&u00[q]);
                            float2 f01 = __half22float2(*(const __half2*)&u01[q]);
                            float2 f10 = __half22float2(*(const __half2*)&u10[q]);
                            float2 f11 = __half22float2(*(const __half2*)&u11[q]);
                            acc[2*q]   += w00*f00.x + w01*f01.x + w10*f10.x + w11*f11.x;
                            acc[2*q+1] += w00*f00.y + w01*f01.y + w10*f10.y + w11*f11.y;
                        }
                    }
                }
            }
            int c = cg*8;                      // local channel within this half
            #pragma unroll
            for (int j = 0; j < 8; j++)
                sout[(c+j)*NBIN + bin] = acc[j] * 0.25f;
        }
    }
    __syncthreads();
    size_t base = (size_t)roi * FDIM + (size_t)cb * POOL_HALF;
    float* o = out + base;
    if (EMIT_HALF) {
        __half* oh = out_h + base;
        for (int i = tid; i < POOL_HALF; i += 256) {
            float v = sout[i];
            o[i] = v;
            oh[i] = __float2half_rn(v);
        }
    } else {
        for (int i = tid; i < POOL_HALF; i += 256) o[i] = sout[i];
    }

    if (RESCALE) {
        const float4* s4 = (const float4*)sout;
        int wo = cb * PH4;
        float s[4] = {0.f, 0.f, 0.f, 0.f};
        for (int k = tid; k < PH4; k += 256) {
            float4 v = s4[k];
            #pragma unroll
            for (int j = 0; j < 4; j++) {
                float4 a = rw4[(size_t)j*(FDIM/4) + wo + k];
                s[j] += v.x*a.x + v.y*a.y + v.z*a.z + v.w*a.w;
            }
        }
        #pragma unroll
        for (int o2 = 16; o2 > 0; o2 >>= 1)
            #pragma unroll
            for (int j = 0; j < 4; j++)
                s[j] += __shfl_down_sync(0xffffffffu, s[j], o2);
        __shared__ float red[4][8];
        int lane = tid & 31, warp = tid >> 5;
        if (lane == 0) { red[0][warp]=s[0]; red[1][warp]=s[1]; red[2][warp]=s[2]; red[3][warp]=s[3]; }
        __syncthreads();
        if (tid < 4) {
            float t = 0.f;
            #pragma unroll
            for (int ww = 0; ww < 8; ww++) t += red[tid][ww];
            g_dots[roi*8 + cb*4 + tid] = t;
        }
    }
}

// ------------ fp16 tensor-core NT GEMM, 128x128x32, 3-stage cp.async --------
// Partials stored as fp16 (half2 packed stores).
__device__ __forceinline__ void mma_f16(float* c, uint32_t a0, uint32_t a1,
                                        uint32_t a2, uint32_t a3,
                                        uint32_t b0, uint32_t b1) {
    asm volatile(
        "mma.sync.aligned.m16n8k16.row.col.f32.f16.f16.f32 "
        "{%0,%1,%2,%3}, {%4,%5,%6,%7}, {%8,%9}, {%0,%1,%2,%3};"
        : "+f"(c[0]), "+f"(c[1]), "+f"(c[2]), "+f"(c[3])
        : "r"(a0), "r"(a1), "r"(a2), "r"(a3), "r"(b0), "r"(b1));
}
__device__ __forceinline__ uint32_t s2u(const void* p) {
    return (uint32_t)__cvta_generic_to_shared(p);
}
__device__ __forceinline__ void cp16(uint32_t dst, const void* src) {
    asm volatile("cp.async.cg.shared.global [%0], [%1], 16;" :: "r"(dst), "l"(src));
}

__global__ void __launch_bounds__(256, 2)
gemm_h(const __half* __restrict__ A, const __half* __restrict__ B,
       __half* __restrict__ P, int N, int K) {
    const int BM = 128, BN = 128;
    __shared__ __align__(16) uint32_t As[3][BM*16];
    __shared__ __align__(16) uint32_t Bs[3][BN*16];

    int tid  = threadIdx.x;
    int lane = tid & 31, w = tid >> 5;
    int g = lane >> 2, tig = lane & 3;
    int wm = w >> 2, wn = w & 3;               // 2 x 4 warp grid
    int bm = blockIdx.y * BM, bn = blockIdx.x * BN;
    int S  = gridDim.z, kz = blockIdx.z;
    int Ks = K / S;
    int M  = gridDim.y * BM;
    int nst = Ks >> 5;

    int lm = tid >> 2, lq = tid & 3;
    const __half* Ap0 = A + (size_t)(bm + lm)*K + (size_t)kz*Ks + lq*8;
    const __half* Ap1 = Ap0 + (size_t)64*K;
    const __half* Bp0 = B + (size_t)(bn + lm)*K + (size_t)kz*Ks + lq*8;
    const __half* Bp1 = Bp0 + (size_t)64*K;
    int sc = lq ^ ((lm >> 1) & 3);
    int sw0 = lm*16 + sc*4;
    int sw1 = (lm + 64)*16 + sc*4;
    uint32_t sa0[3], sa1[3], sb0[3], sb1[3];
    #pragma unroll
    for (int b3 = 0; b3 < 3; b3++) {
        sa0[b3] = s2u(&As[b3][sw0]);  sa1[b3] = s2u(&As[b3][sw1]);
        sb0[b3] = s2u(&Bs[b3][sw0]);  sb1[b3] = s2u(&Bs[b3][sw1]);
    }

    float acc[4][4][4];
    #pragma unroll
    for (int i = 0; i < 4; i++)
        #pragma unroll
        for (int j = 0; j < 4; j++)
            #pragma unroll
            for (int q = 0; q < 4; q++) acc[i][j][q] = 0.0f;

    int mrow[4], mj[4];
    #pragma unroll
    for (int ii = 0; ii < 4; ii++) {
        mrow[ii] = wm*64 + ii*16 + g;
        mj[ii] = ((mrow[ii] >> 1) & 3) << 2;
    }
    int nrow[4], nj[4];
    #pragma unroll
    for (int jj = 0; jj < 4; jj++) {
        nrow[jj] = wn*32 + jj*8 + g;
        nj[jj] = ((nrow[jj] >> 1) & 3) << 2;
    }

    cp16(sa0[0], Ap0);  cp16(sa1[0], Ap1);
    cp16(sb0[0], Bp0);  cp16(sb1[0], Bp1);
    asm volatile("cp.async.commit_group;");
    if (nst > 1) {
        cp16(sa0[1], Ap0 + 32);  cp16(sa1[1], Ap1 + 32);
        cp16(sb0[1], Bp0 + 32);  cp16(sb1[1], Bp1 + 32);
        asm volatile("cp.async.commit_group;");
    }

    int buf = 0;
    for (int s = 0; s < nst; s++) {
        if (s < nst - 1) asm volatile("cp.async.wait_group 1;");
        else             asm volatile("cp.async.wait_group 0;");
        __syncthreads();

        const uint32_t* as = As[buf];
        const uint32_t* bs = Bs[buf];
        #pragma unroll
        for (int kb = 0; kb < 2; kb++) {
            int kw0 = kb*8 + tig, kw1 = kw0 + 4;
            uint32_t af[4][4], bf[4][2];
            #pragma unroll
            for (int jj = 0; jj < 4; jj++) {
                int rn = nrow[jj]*16, x = nj[jj];
                bf[jj][0] = bs[rn + (kw0 ^ x)];
                bf[jj][1] = bs[rn + (kw1 ^ x)];
            }
            #pragma unroll
            for (int ii = 0; ii < 4; ii++) {
                int r0 = mrow[ii]*16, r1 = (mrow[ii]+8)*16, x = mj[ii];
                af[ii][0] = as[r0 + (kw0 ^ x)];
                af[ii][1] = as[r1 + (kw0 ^ x)];
                af[ii][2] = as[r0 + (kw1 ^ x)];
                af[ii][3] = as[r1 + (kw1 ^ x)];
            }
            #pragma unroll
            for (int ii = 0; ii < 4; ii++)
                #pragma unroll
                for (int jj = 0; jj < 4; jj++)
                    mma_f16(acc[ii][jj], af[ii][0], af[ii][1], af[ii][2], af[ii][3],
                            bf[jj][0], bf[jj][1]);
        }

        if (s + 2 < nst) {
            int nb = (buf + 2) % 3;
            size_t o = (size_t)(s+2)*32;
            cp16(sa0[nb], Ap0 + o);  cp16(sa1[nb], Ap1 + o);
            cp16(sb0[nb], Bp0 + o);  cp16(sb1[nb], Bp1 + o);
            asm volatile("cp.async.commit_group;");
        }
        buf = (buf + 1) % 3;
    }

    __half* Pp = P + (size_t)kz * M * N;
    #pragma unroll
    for (int ii = 0; ii < 4; ii++) {
        #pragma unroll
        for (int jj = 0; jj < 4; jj++) {
            int r0 = bm + wm*64 + ii*16 + g;
            int c0 = bn + wn*32 + jj*8 + tig*2;
            *(uint32_t*)(Pp + (size_t)r0*N + c0) =
                h2u(__floats2half2_rn(acc[ii][jj][0], acc[ii][jj][1]));
            *(uint32_t*)(Pp + (size_t)(r0+8)*N + c0) =
                h2u(__floats2half2_rn(acc[ii][jj][2], acc[ii][jj][3]));
        }
    }
}

// -------- split-K combine (8 halves/thread): act(sum_s P_s + bias) ----------
__global__ void combine8h(const __half* __restrict__ P, const float* __restrict__ bias,
                          __half* __restrict__ outh, int M, int N, int S) {
    int i = blockIdx.x * 256 + threadIdx.x;   // over M*N/8
    if (i >= M*N/8) return;
    int base = i*8;
    int m = base / N, n = base - m*N;
    float v[8];
    float4 b0 = *(const float4*)(bias + n);
    float4 b1 = *(const float4*)(bias + n + 4);
    v[0]=b0.x; v[1]=b0.y; v[2]=b0.z; v[3]=b0.w;
    v[4]=b1.x; v[5]=b1.y; v[6]=b1.z; v[7]=b1.w;
    for (int s = 0; s < S; s++) {
        uint4 p = *(const uint4*)(P + ((size_t)s*M + m)*N + n);
        const uint32_t* pu = &p.x;
        #pragma unroll
        for (int q = 0; q < 4; q++) {
            float2 f = __half22float2(*(const __half2*)&pu[q]);
            v[2*q]   += f.x;
            v[2*q+1] += f.y;
        }
    }
    uint4 o;
    uint32_t* ou = &o.x;
    #pragma unroll
    for (int q = 0; q < 4; q++) {
        float a = fmaxf(v[2*q],   0.f);
        float b = fmaxf(v[2*q+1], 0.f);
        ou[q] = h2u(__floats2half2_rn(a, b));
    }
    *(uint4*)(outh + base) = o;
}

// -------- final combine (float out, ragged N) + fused new-roi finalize ------
#define CF_BLOCKS ((NROIS*NOFF + 255)/256)    // 196
__global__ void combine_f_fin(const __half* __restrict__ P, const float* __restrict__ bias,
                              float* __restrict__ outf, int M, int Ntot, int Nlog, int S,
                              const float* __restrict__ rois,
                              const float* __restrict__ rbias) {
    if (blockIdx.x >= CF_BLOCKS) {
        int roi = (blockIdx.x - CF_BLOCKS) * 256 + threadIdx.x;
        if (roi >= NROIS) return;
        float d[4];
        #pragma unroll
        for (int j = 0; j < 4; j++) {
            float t = g_dots[roi*8 + j] + g_dots[roi*8 + 4 + j] + rbias[j];
            d[j] = 1.0f + 0.5f / (1.0f + expf(-t));
        }
        const float* r = rois + roi*5;
        float cx = (r[1] + r[3]) * 0.5f + d[0];
        float cy = (r[2] + r[4]) * 0.5f + d[1];
        float nw = (r[3] - r[1]) * d[2];
        float nh = (r[4] - r[2]) * d[3];
        float* nr = g_nrois + roi*5;
        nr[0] = r[0];
        nr[1] = cx - 0.5f*nw;  nr[2] = cy - 0.5f*nh;
        nr[3] = cx + 0.5f*nw;  nr[4] = cy + 0.5f*nh;
        return;
    }
    int i = blockIdx.x * 256 + threadIdx.x;
    if (i >= M*Nlog) return;
    int m = i / Nlog, n = i - m*Nlog;
    float v = bias[n];
    for (int s = 0; s < S; s++)
        v += __half2float(P[((size_t)s*M + m)*Ntot + n]);
    outf[i] = v;
}

// ---------------- launch -----------------------------------------------------
extern "C" void kernel_launch(void* const* d_in, const int* in_sizes, int n_in,
                              void* d_out, int out_size) {
    const float* input     = (const float*)d_in[0];
    const float* rois      = (const float*)d_in[1];
    const float* rescale_w = (const float*)d_in[2];
    const float* rescale_b = (const float*)d_in[3];
    const float* off_w1    = (const float*)d_in[4];
    const float* off_b1    = (const float*)d_in[5];
    const float* off_w2    = (const float*)d_in[6];
    const float* off_b2    = (const float*)d_in[7];
    const float* off_w3    = (const float*)d_in[8];
    const float* off_b3    = (const float*)d_in[9];

    float* xcls = (float*)d_out;
    float* xreg = xcls + (size_t)NROIS * FDIM;

    __half *a1p, *w1p, *w2p, *w3p, *h1p, *h2p, *partp;
    float *offp, *nroisp;
    cudaGetSymbolAddress((void**)&a1p,    g_a1h);
    cudaGetSymbolAddress((void**)&w1p,    g_w1h);
    cudaGetSymbolAddress((void**)&w2p,    g_w2h);
    cudaGetSymbolAddress((void**)&w3p,    g_w3h);
    cudaGetSymbolAddress((void**)&h1p,    g_h1h);
    cudaGetSymbolAddress((void**)&h2p,    g_h2h);
    cudaGetSymbolAddress((void**)&offp,   g_off);
    cudaGetSymbolAddress((void**)&nroisp, g_nrois);
    cudaGetSymbolAddress((void**)&partp,  g_parth);

    // 1) transpose to NHWC fp16
    nchw2nhwc_h<<<dim3(HW/32, CH/64, BATCH), dim3(32, 8)>>>(input);
    // 2) x_cls pool (2 CTAs/ROI) + rescale dots + fused weight conversion
    roi_pool<false,true,true,true><<<dim3(NROIS, 3), 256>>>(
        rois, nullptr, xcls, a1p, (const float4*)rescale_w,
        off_w1, off_w2, off_w3);
    // 3) offset MLP: fp16 tensor cores (3-stage cp.async), fp16 split-K partials
    gemm_h<<<dim3(DFC/128, NROIS/128, 8), 256>>>(a1p, w1p, partp, DFC, FDIM);
    combine8h<<<(NROIS*DFC/8 + 255)/256, 256>>>(partp, off_b1, h1p, NROIS, DFC, 8);
    gemm_h<<<dim3(DFC/128, NROIS/128, 8), 256>>>(h1p, w2p, partp, DFC, DFC);
    combine8h<<<(NROIS*DFC/8 + 255)/256, 256>>>(partp, off_b2, h2p, NROIS, DFC, 8);
    gemm_h<<<dim3(1, NROIS/128, 8), 256>>>(h2p, w3p, partp, NOFFP, DFC);
    // 4) final combine + fused new-roi finalize
    combine_f_fin<<<CF_BLOCKS + 2, 256>>>(partp, off_b3, offp, NROIS, NOFFP, NOFF, 8,
                                          rois, rescale_b);
    // 5) x_reg pool (2 CTAs/ROI) -> second half of d_out
    roi_pool<true,false,false,false><<<dim3(NROIS, 2), 256>>>(
        nroisp, offp, xreg, nullptr, nullptr, nullptr, nullptr, nullptr);
}